// round 13
// baseline (speedup 1.0000x reference)
#include <cuda_runtime.h>
#include <math.h>

#define Bn 8
#define C0 16
#define C1c 64
#define C2c 64
#define Tt 12
#define TP 10
#define T2 8
#define Nn 256
#define KTc 3
#define Hh 8
#define ALPHA 0.2f
#define DMAX 64
#define XSZ (Bn*TP*Nn*C1c)   // 1310720

// scratch (static device allocations — allowed)
__device__ float g_xg[XSZ];          // x_t1 in [b,t,n,c]
__device__ float g_xs[XSZ];          // x_t1 + gat -> x_s
__device__ float g_y[Bn*T2*C2c*Nn];  // conv2+relu output, [bt][c][n]
__device__ float g_psum[Bn*T2*4*2*2];// per (bt, cs, nhalf) partial LN sums
__device__ float g_e1[Bn*TP*Hh*Nn];  // e1[bt][h][n]
__device__ float g_e2[Bn*TP*Hh*Nn];  // e2[bt][h][n]
__device__ int   g_deg[Nn];
__device__ unsigned char g_nbr8[Nn*DMAX];
__device__ float g_vT[64*16];        // vT[c*16 + h*2+half]
__device__ float g_lnwT[C2c*Nn];
__device__ float g_lnbT[C2c*Nn];
__device__ unsigned int g_cnt[Bn*4]; // per (b, t2pair) arrival counter (wraps)

__device__ __forceinline__ float tanh_ap(float x) {
    float y;
    asm("tanh.approx.f32 %0, %1;" : "=f"(y) : "f"(x));
    return y;
}

// ---------------------------------------------------------------------------
// Kernel A: conv1 (KT=3) + GLU, grid (9, TP, B), 128 threads.
// q<8: conv octant. q==8: preprocessing (adjacency byte-lists, LN transpose,
// v vectors) running concurrently.
// ---------------------------------------------------------------------------
__global__ void kA(const float* __restrict__ x,
                   const float* __restrict__ w1,
                   const float* __restrict__ b1,
                   const float* __restrict__ adj,
                   const float* __restrict__ lnw,
                   const float* __restrict__ lnb,
                   const float* __restrict__ Wh,
                   const float* __restrict__ ah) {
    extern __shared__ float sm[];
    int tid = threadIdx.x;
    int q = blockIdx.x, t = blockIdx.y, b = blockIdx.z;

    if (q == 8) {   // ---- preprocessing slice ----
        int slot = t*8 + b;
        int w = tid >> 5, lane = tid & 31;
        if (slot < 32) {
            #pragma unroll
            for (int rr = 0; rr < 2; rr++) {
                int i = slot*8 + rr*4 + w;
                int cnt = 0;
                #pragma unroll
                for (int cc = 0; cc < 8; cc++) {
                    float av = adj[i*Nn + cc*32 + lane];
                    unsigned m = __ballot_sync(0xffffffffu, av > 0.0f);
                    if (av > 0.0f) {
                        int pos = cnt + __popc(m & ((1u << lane) - 1u));
                        if (pos < DMAX)
                            g_nbr8[i*DMAX + pos] = (unsigned char)(cc*32 + lane);
                    }
                    cnt += __popc(m);
                }
                if (lane == 0) g_deg[i] = (cnt > DMAX) ? DMAX : cnt;
            }
        } else if (slot < 40) {
            int p = slot - 32;
            #pragma unroll
            for (int k = 0; k < 16; k++) {
                int idx = p*2048 + k*128 + tid;
                int c = idx >> 8, n2 = idx & 255;
                g_lnwT[idx] = lnw[n2*C2c + c];
                g_lnbT[idx] = lnb[n2*C2c + c];
            }
        } else if (slot == 40) {
            #pragma unroll
            for (int r = 0; r < 8; r++) {
                int id = tid + r*128;
                int j = id & 15, c = id >> 4;     // j = h*2 + half
                int h = j >> 1, half = j & 1;
                const float* wr = Wh + (h*64 + c)*64;
                const float* ar = ah + h*128 + half*64;
                float s = 0.0f;
                #pragma unroll
                for (int d2 = 0; d2 < 64; d2++) s = fmaf(wr[d2], ar[d2], s);
                g_vT[c*16 + j] = s;
            }
        }
        return;
    }

    // ---- conv1 + GLU ----
    float*  sx  = sm;                       // 48*128 = 6144 (reused as sxt 16*129)
    float4* swp = (float4*)(sm + 6144);     // 16*24 float4
    int nh = q & 1, ch = q >> 1;
    int n0 = nh * 128;

    #pragma unroll
    for (int u = 0; u < 48; u++) {
        sx[u*128 + tid] = x[((b*C0 + u/3)*Tt + t + (u%3))*Nn + n0 + tid];
    }
    for (int idx = tid; idx < 16*24; idx += 128) {
        int cl = idx / 24, k2 = idx % 24;
        int c = ch*16 + cl;
        float4 v;
        v.x = w1[c*48 + 2*k2];
        v.y = w1[c*48 + 2*k2 + 1];
        v.z = w1[(c+64)*48 + 2*k2];
        v.w = w1[(c+64)*48 + 2*k2 + 1];
        swp[idx] = v;
    }
    __syncthreads();

    int nl = tid;
    float xr[48];
    #pragma unroll
    for (int k = 0; k < 48; k++) xr[k] = sx[k*128 + nl];
    __syncthreads();

    #pragma unroll
    for (int cl = 0; cl < 16; cl++) {
        int c = ch*16 + cl;
        float am = __ldg(b1 + c);
        float ag = __ldg(b1 + c + 64);
        #pragma unroll
        for (int k2 = 0; k2 < 24; k2++) {
            float4 w = swp[cl*24 + k2];
            am = fmaf(xr[2*k2],   w.x, am);
            am = fmaf(xr[2*k2+1], w.y, am);
            ag = fmaf(xr[2*k2],   w.z, ag);
            ag = fmaf(xr[2*k2+1], w.w, ag);
        }
        float xin = (c < C0) ? xr[c*3 + 2] : 0.0f;
        float val = (am + xin) * (1.0f / (1.0f + __expf(-ag)));
        sx[cl*129 + nl] = val;
    }
    __syncthreads();

    int base = ((b*TP + t)*Nn + n0)*C1c + ch*16;
    for (int idx = tid; idx < 128*16; idx += 128) {
        int n2 = idx >> 4, cl = idx & 15;
        g_xg[base + n2*64 + cl] = sx[cl*129 + n2];
    }
}

// ---------------------------------------------------------------------------
// Kernel V: e1/e2 for all (h, n) of each (b,t). grid (TP, B), 256 threads.
// ---------------------------------------------------------------------------
__global__ void kV() {
    __shared__ float svT[1024];
    int t = blockIdx.x, b = blockIdx.y;
    int bt = b*TP + t;
    int n = threadIdx.x;
    for (int idx = n; idx < 1024; idx += 256) svT[idx] = g_vT[idx];
    __syncthreads();

    float a1[8], a2[8];
    #pragma unroll
    for (int h = 0; h < 8; h++) { a1[h] = 0.0f; a2[h] = 0.0f; }

    const float4* xrow = (const float4*)(g_xg + bt*Nn*C1c + n*64);
    #pragma unroll
    for (int g = 0; g < 16; g++) {
        float4 xv = xrow[g];
        float xs[4] = {xv.x, xv.y, xv.z, xv.w};
        #pragma unroll
        for (int e = 0; e < 4; e++) {
            float xe = xs[e];
            const float4* vq = (const float4*)(svT + (4*g + e)*16);
            float4 q0 = vq[0], q1 = vq[1], q2 = vq[2], q3 = vq[3];
            a1[0] = fmaf(xe, q0.x, a1[0]); a2[0] = fmaf(xe, q0.y, a2[0]);
            a1[1] = fmaf(xe, q0.z, a1[1]); a2[1] = fmaf(xe, q0.w, a2[1]);
            a1[2] = fmaf(xe, q1.x, a1[2]); a2[2] = fmaf(xe, q1.y, a2[2]);
            a1[3] = fmaf(xe, q1.z, a1[3]); a2[3] = fmaf(xe, q1.w, a2[3]);
            a1[4] = fmaf(xe, q2.x, a1[4]); a2[4] = fmaf(xe, q2.y, a2[4]);
            a1[5] = fmaf(xe, q2.z, a1[5]); a2[5] = fmaf(xe, q2.w, a2[5]);
            a1[6] = fmaf(xe, q3.x, a1[6]); a2[6] = fmaf(xe, q3.y, a2[6]);
            a1[7] = fmaf(xe, q3.z, a1[7]); a2[7] = fmaf(xe, q3.w, a2[7]);
        }
    }
    #pragma unroll
    for (int h = 0; h < 8; h++) {
        g_e1[bt*2048 + h*256 + n] = a1[h];
        g_e2[bt*2048 + h*256 + n] = a2[h];
    }
}

// ---------------------------------------------------------------------------
// Kernel Agg: all-8-head GAT + residual -> x_s. grid (4, TP, B), 256 threads.
// HALF-WARP PER ROW (2 rows/warp). sxg group-XOR swizzle, aligned LDS128.
// ---------------------------------------------------------------------------
__global__ void kAgg() {
    extern __shared__ float sm[];
    float* sxg   = sm;                 // 256*64 = 16384 (swizzled groups)
    float* se2   = sxg + 16384;        // 8*256 = 2048
    float* se1   = se2 + 2048;         // 8*64  = 512
    float* stash = se1 + 512;          // 8 warps * 1056 (2x512 p + 128B nbr)
    int tid = threadIdx.x;
    int q = blockIdx.x, t = blockIdx.y, b = blockIdx.z;
    int bt = b*TP + t;
    int base = bt*Nn*C1c;
    int i0 = q*64;

    for (int idx = tid; idx < 4096; idx += 256) {
        float4 v = ((const float4*)(g_xg + base))[idx];
        int n2 = idx >> 4, g = idx & 15;
        *(float4*)&sxg[n2*64 + ((g ^ (n2 & 15)) << 2)] = v;
    }
    for (int idx = tid; idx < 512; idx += 256) {
        float4 v = ((const float4*)(g_e2 + bt*2048))[idx];
        int o = idx*4;
        se2[o] = v.x; se2[o+1] = v.y; se2[o+2] = v.z; se2[o+3] = v.w;
    }
    for (int idx = tid; idx < 512; idx += 256) {
        int h = idx >> 6, il = idx & 63;
        se1[idx] = g_e1[bt*2048 + h*256 + i0 + il];
    }
    __syncthreads();

    int w = tid >> 5, lane = tid & 31;
    int rowSel = lane >> 4, hl = lane & 15;
    float* spw   = stash + w*1056;          // [spA 512][spB 512][nbr 128B]
    float* spMy  = spw + rowSel*512;
    unsigned char* snbMy = (unsigned char*)(spw + 1024) + rowSel*64;

    for (int rr = 0; rr < 4; rr++) {
        int il = w*8 + rr*2 + rowSel;
        int i = i0 + il;
        int d = g_deg[i];
        int dOther = __shfl_xor_sync(0xffffffffu, d, 16);
        int kmax = (d > dOther) ? d : dOther;

        float e1v[8];
        #pragma unroll
        for (int h = 0; h < 8; h++) e1v[h] = se1[h*64 + il];

        // stage A: slots k = hl + 16s, both rows in parallel
        float S[8];
        #pragma unroll
        for (int h = 0; h < 8; h++) S[h] = 0.0f;
        #pragma unroll
        for (int s = 0; s < 4; s++) {
            int k = hl + s*16;
            float4 pa = {0.f,0.f,0.f,0.f}, pb = {0.f,0.f,0.f,0.f};
            int j = 0;
            if (k < d) {
                j = g_nbr8[i*DMAX + k];
                float s0 = e1v[0] + se2[0*256 + j];
                float s1 = e1v[1] + se2[1*256 + j];
                float s2 = e1v[2] + se2[2*256 + j];
                float s3 = e1v[3] + se2[3*256 + j];
                pa.x = __expf(fmaxf(s0, ALPHA*s0));
                pa.y = __expf(fmaxf(s1, ALPHA*s1));
                pa.z = __expf(fmaxf(s2, ALPHA*s2));
                pa.w = __expf(fmaxf(s3, ALPHA*s3));
                float s4 = e1v[4] + se2[4*256 + j];
                float s5 = e1v[5] + se2[5*256 + j];
                float s6 = e1v[6] + se2[6*256 + j];
                float s7 = e1v[7] + se2[7*256 + j];
                pb.x = __expf(fmaxf(s4, ALPHA*s4));
                pb.y = __expf(fmaxf(s5, ALPHA*s5));
                pb.z = __expf(fmaxf(s6, ALPHA*s6));
                pb.w = __expf(fmaxf(s7, ALPHA*s7));
            }
            snbMy[k] = (unsigned char)j;
            *(float4*)&spMy[k*8]     = pa;
            *(float4*)&spMy[k*8 + 4] = pb;
            S[0] += pa.x; S[1] += pa.y; S[2] += pa.z; S[3] += pa.w;
            S[4] += pb.x; S[5] += pb.y; S[6] += pb.z; S[7] += pb.w;
        }
        // half-warp butterfly: full sums per row
        #pragma unroll
        for (int o = 8; o > 0; o >>= 1) {
            #pragma unroll
            for (int h = 0; h < 8; h++)
                S[h] += __shfl_xor_sync(0xffffffffu, S[h], o);
        }
        __syncwarp();

        // stage B: gather, 4 logical channels per lane (cbase = 4*hl)
        float a[32];
        #pragma unroll
        for (int u = 0; u < 32; u++) a[u] = 0.0f;

        int k = 0;
        for (; k + 2 <= kmax; k += 2) {
            int ja = snbMy[k], jb = snbMy[k+1];
            float4 pa0 = *(const float4*)&spMy[k*8];
            float4 pa1 = *(const float4*)&spMy[k*8 + 4];
            float4 pb0 = *(const float4*)&spMy[(k+1)*8];
            float4 pb1 = *(const float4*)&spMy[(k+1)*8 + 4];
            float4 xa = *(const float4*)&sxg[ja*64 + ((hl ^ (ja & 15)) << 2)];
            float4 xb = *(const float4*)&sxg[jb*64 + ((hl ^ (jb & 15)) << 2)];
            float xav[4] = {xa.x, xa.y, xa.z, xa.w};
            float xbv[4] = {xb.x, xb.y, xb.z, xb.w};
            float pav[8] = {pa0.x, pa0.y, pa0.z, pa0.w, pa1.x, pa1.y, pa1.z, pa1.w};
            float pbv[8] = {pb0.x, pb0.y, pb0.z, pb0.w, pb1.x, pb1.y, pb1.z, pb1.w};
            #pragma unroll
            for (int h = 0; h < 8; h++) {
                #pragma unroll
                for (int e = 0; e < 4; e++) {
                    a[h*4+e] = fmaf(pav[h], xav[e], a[h*4+e]);
                    a[h*4+e] = fmaf(pbv[h], xbv[e], a[h*4+e]);
                }
            }
        }
        if (k < kmax) {
            int j = snbMy[k];
            float4 p0 = *(const float4*)&spMy[k*8];
            float4 p1 = *(const float4*)&spMy[k*8 + 4];
            float4 xv = *(const float4*)&sxg[j*64 + ((hl ^ (j & 15)) << 2)];
            float xsv[4] = {xv.x, xv.y, xv.z, xv.w};
            float pv[8] = {p0.x, p0.y, p0.z, p0.w, p1.x, p1.y, p1.z, p1.w};
            #pragma unroll
            for (int h = 0; h < 8; h++)
                #pragma unroll
                for (int e = 0; e < 4; e++)
                    a[h*4+e] = fmaf(pv[h], xsv[e], a[h*4+e]);
        }

        float rs[8];
        #pragma unroll
        for (int h = 0; h < 8; h++) rs[h] = 1.0f / S[h];
        float r[4] = {0.0f, 0.0f, 0.0f, 0.0f};
        #pragma unroll
        for (int h = 0; h < 8; h++) {
            #pragma unroll
            for (int e = 0; e < 4; e++)
                r[e] += tanh_ap(a[h*4+e] * rs[h]);
        }
        float4 x0 = *(const float4*)&sxg[i*64 + ((hl ^ (i & 15)) << 2)];
        float4 o;
        o.x = x0.x + r[0]*0.125f;
        o.y = x0.y + r[1]*0.125f;
        o.z = x0.z + r[2]*0.125f;
        o.w = x0.w + r[3]*0.125f;
        *(float4*)&g_xs[base + i*64 + 4*hl] = o;
        __syncwarp();   // stash reused next pair
    }
}

// ---------------------------------------------------------------------------
// Kernel D1: conv2 + residual + relu + partial LN stats, t2-paired, n-split,
// PLUS fused LN epilogue (threadfence reduction — last arriving of the 8
// blocks per (b,t2pair) normalizes and stores both t2 slices).
// grid (8, B, 4), 256 threads. Mainloop identical to the R11-measured 25.9us
// version (full unroll, NO launch_bounds).
// ---------------------------------------------------------------------------
__global__ void kD1(const float* __restrict__ w2, const float* __restrict__ b2,
                    float* __restrict__ out) {
    extern __shared__ float sm[];
    float* sx2  = sm;            // 4*128*17 = 8704
    float* sw2a = sm + 8704;     // 4*48*16 = 3072
    __shared__ float red[32];
    __shared__ unsigned int sLast;
    int tid = threadIdx.x;
    int t2p = blockIdx.x >> 1, nh = blockIdx.x & 1;
    int b = blockIdx.y, cs = blockIdx.z;
    int half = tid >> 7, nl = tid & 127;
    int t2a = t2p*2;
    int bT = b*TP + t2a;
    int n0 = nh*128;

    for (int idx = tid; idx < 4*48*16; idx += 256) {
        int cout = idx & 15;
        int r = idx >> 4;
        int g = r / 48;
        int ck = r % 48;
        int ci = ck / 3, kt = ck % 3;
        sw2a[idx] = w2[(cs*16 + cout)*(C1c*KTc) + (g*16 + ci)*KTc + kt];
    }

    float acc[16];
    #pragma unroll
    for (int cc = 0; cc < 8; cc++) {
        float bb = __ldg(b2 + cs*16 + half*8 + cc);
        acc[cc] = bb; acc[8 + cc] = bb;
    }

    int ci_s = tid & 15, r0 = tid >> 4;

    #pragma unroll
    for (int g = 0; g < 4; g++) {
        __syncthreads();
        #pragma unroll
        for (int u = 0; u < 32; u++) {
            int linear = r0 + 16*u;
            int kt = linear >> 7, nn = linear & 127;
            sx2[(kt*128 + nn)*17 + ci_s] =
                g_xs[((bT + kt)*Nn + n0 + nn)*C1c + g*16 + ci_s];
        }
        __syncthreads();

        #pragma unroll 4
        for (int ci = 0; ci < 16; ci++) {
            #pragma unroll
            for (int kt = 0; kt < 3; kt++) {
                float xva = sx2[(kt*128 + nl)*17 + ci];
                float xvb = sx2[((kt + 1)*128 + nl)*17 + ci];
                const float4* wr = (const float4*)(sw2a + (g*48 + ci*3 + kt)*16 + half*8);
                float4 w0 = wr[0], w1v = wr[1];
                acc[0]  = fmaf(xva, w0.x,  acc[0]);
                acc[1]  = fmaf(xva, w0.y,  acc[1]);
                acc[2]  = fmaf(xva, w0.z,  acc[2]);
                acc[3]  = fmaf(xva, w0.w,  acc[3]);
                acc[4]  = fmaf(xva, w1v.x, acc[4]);
                acc[5]  = fmaf(xva, w1v.y, acc[5]);
                acc[6]  = fmaf(xva, w1v.z, acc[6]);
                acc[7]  = fmaf(xva, w1v.w, acc[7]);
                acc[8]  = fmaf(xvb, w0.x,  acc[8]);
                acc[9]  = fmaf(xvb, w0.y,  acc[9]);
                acc[10] = fmaf(xvb, w0.z,  acc[10]);
                acc[11] = fmaf(xvb, w0.w,  acc[11]);
                acc[12] = fmaf(xvb, w1v.x, acc[12]);
                acc[13] = fmaf(xvb, w1v.y, acc[13]);
                acc[14] = fmaf(xvb, w1v.z, acc[14]);
                acc[15] = fmaf(xvb, w1v.w, acc[15]);
            }
        }
        if (g == cs) {
            #pragma unroll
            for (int cc = 0; cc < 8; cc++) {
                acc[cc]     += sx2[(2*128 + nl)*17 + half*8 + cc];
                acc[8 + cc] += sx2[(3*128 + nl)*17 + half*8 + cc];
            }
        }
    }

    float lsA = 0.0f, lssA = 0.0f, lsB = 0.0f, lssB = 0.0f;
    #pragma unroll
    for (int cc = 0; cc < 8; cc++) {
        float va = fmaxf(acc[cc], 0.0f);
        float vb = fmaxf(acc[8 + cc], 0.0f);
        acc[cc] = va; acc[8 + cc] = vb;
        lsA += va; lssA = fmaf(va, va, lssA);
        lsB += vb; lssB = fmaf(vb, vb, lssB);
    }
    #pragma unroll
    for (int o = 16; o > 0; o >>= 1) {
        lsA  += __shfl_xor_sync(0xffffffffu, lsA,  o);
        lssA += __shfl_xor_sync(0xffffffffu, lssA, o);
        lsB  += __shfl_xor_sync(0xffffffffu, lsB,  o);
        lssB += __shfl_xor_sync(0xffffffffu, lssB, o);
    }
    int w = tid >> 5, lane = tid & 31;
    if (lane == 0) {
        red[w] = lsA; red[w + 8] = lssA;
        red[w + 16] = lsB; red[w + 24] = lssB;
    }
    __syncthreads();
    if (tid == 0) {
        float SA = 0, SSA = 0, SB = 0, SSB = 0;
        #pragma unroll
        for (int i = 0; i < 8; i++) {
            SA += red[i]; SSA += red[i + 8];
            SB += red[i + 16]; SSB += red[i + 24];
        }
        int btA = b*T2 + t2a;
        g_psum[((btA*4 + cs)*2 + nh)*2]     = SA;
        g_psum[((btA*4 + cs)*2 + nh)*2 + 1] = SSA;
        g_psum[(((btA+1)*4 + cs)*2 + nh)*2]     = SB;
        g_psum[(((btA+1)*4 + cs)*2 + nh)*2 + 1] = SSB;
    }

    int ybaseA = ((b*T2 + t2a)*C2c + cs*16 + half*8)*Nn + n0;
    int ybaseB = ybaseA + C2c*Nn;
    #pragma unroll
    for (int cc = 0; cc < 8; cc++) {
        g_y[ybaseA + cc*Nn + nl] = acc[cc];
        g_y[ybaseB + cc*Nn + nl] = acc[8 + cc];
    }

    // ---- fused LN epilogue (threadfence reduction; wrap counter is
    // graph-replay-safe; output deterministic regardless of arrival order) ----
    __syncthreads();
    if (tid == 0) {
        __threadfence();
        unsigned int old = atomicInc(&g_cnt[b*4 + t2p], 7);
        sLast = (old == 7) ? 1u : 0u;
    }
    __syncthreads();
    if (sLast) {
        __threadfence();
        int n = tid;
        #pragma unroll
        for (int tt = 0; tt < 2; tt++) {
            int t2 = t2a + tt;
            int bt = b*T2 + t2;
            float S = 0.0f, SS = 0.0f;
            #pragma unroll
            for (int qq = 0; qq < 8; qq++) {
                S  += g_psum[bt*16 + qq*2];
                SS += g_psum[bt*16 + qq*2 + 1];
            }
            float mu   = S * (1.0f/16384.0f);
            float var  = SS * (1.0f/16384.0f) - mu*mu;
            float rstd = rsqrtf(var + 1e-5f);
            #pragma unroll 8
            for (int c = 0; c < 64; c++) {
                float yv = (g_y[(bt*C2c + c)*Nn + n] - mu) * rstd;
                out[((b*C2c + c)*T2 + t2)*Nn + n] =
                    fmaf(yv, g_lnwT[c*Nn + n], g_lnbT[c*Nn + n]);
            }
        }
    }
}

// ---------------------------------------------------------------------------
extern "C" void kernel_launch(void* const* d_in, const int* in_sizes, int n_in,
                              void* d_out, int out_size) {
    const float* x   = (const float*)d_in[0];
    const float* adj = (const float*)d_in[1];
    const float* w1  = (const float*)d_in[2];
    const float* b1  = (const float*)d_in[3];
    const float* w2  = (const float*)d_in[4];
    const float* b2  = (const float*)d_in[5];
    const float* Wh  = (const float*)d_in[6];
    const float* ah  = (const float*)d_in[7];
    const float* lnw = (const float*)d_in[8];
    const float* lnb = (const float*)d_in[9];
    float* out = (float*)d_out;

    const int smA   = (6144 + 1536) * 4;                 // 30720
    const int smAgg = (16384 + 2048 + 512 + 8*1056) * 4; // 109568
    const int smD   = (8704 + 3072) * 4;                 // 47104
    cudaFuncSetAttribute(kA,   cudaFuncAttributeMaxDynamicSharedMemorySize, smA);
    cudaFuncSetAttribute(kAgg, cudaFuncAttributeMaxDynamicSharedMemorySize, smAgg);
    cudaFuncSetAttribute(kD1,  cudaFuncAttributeMaxDynamicSharedMemorySize, smD);

    kA<<<dim3(9, TP, Bn), 128, smA>>>(x, w1, b1, adj, lnw, lnb, Wh, ah);
    kV<<<dim3(TP, Bn), 256>>>();
    kAgg<<<dim3(4, TP, Bn), 256, smAgg>>>();
    kD1<<<dim3(8, Bn, 4), 256, smD>>>(w2, b2, out);
}

// round 14
// speedup vs baseline: 1.2997x; 1.2997x over previous
#include <cuda_runtime.h>
#include <math.h>

#define Bn 8
#define C0 16
#define C1c 64
#define C2c 64
#define Tt 12
#define TP 10
#define T2 8
#define Nn 256
#define KTc 3
#define Hh 8
#define ALPHA 0.2f
#define DMAX 64
#define XSZ (Bn*TP*Nn*C1c)   // 1310720

// scratch (static device allocations — allowed)
__device__ float g_xg[XSZ];          // x_t1 in [b,t,n,c]
__device__ float g_xs[XSZ];          // x_t1 + gat -> x_s
__device__ float g_y[Bn*T2*C2c*Nn];  // conv2+relu output, [bt][c][n]
__device__ float g_psum[Bn*T2*4*2*2];// per (bt, cs, nhalf) partial LN sums
__device__ int   g_deg[Nn];
__device__ unsigned char g_nbr8[Nn*DMAX];
__device__ float g_vT[64*16];        // vT[c*16 + h*2+half]
__device__ float g_lnwT[C2c*Nn];
__device__ float g_lnbT[C2c*Nn];

__device__ __forceinline__ float tanh_ap(float x) {
    float y;
    asm("tanh.approx.f32 %0, %1;" : "=f"(y) : "f"(x));
    return y;
}

// ---------------------------------------------------------------------------
// Kernel A: conv1 (KT=3) + GLU, grid (9, TP, B), 128 threads.
// q<8: conv octant. q==8: preprocessing (adjacency byte-lists, LN transpose,
// v vectors) running concurrently.
// ---------------------------------------------------------------------------
__global__ void kA(const float* __restrict__ x,
                   const float* __restrict__ w1,
                   const float* __restrict__ b1,
                   const float* __restrict__ adj,
                   const float* __restrict__ lnw,
                   const float* __restrict__ lnb,
                   const float* __restrict__ Wh,
                   const float* __restrict__ ah) {
    extern __shared__ float sm[];
    int tid = threadIdx.x;
    int q = blockIdx.x, t = blockIdx.y, b = blockIdx.z;

    if (q == 8) {   // ---- preprocessing slice ----
        int slot = t*8 + b;
        int w = tid >> 5, lane = tid & 31;
        if (slot < 32) {
            #pragma unroll
            for (int rr = 0; rr < 2; rr++) {
                int i = slot*8 + rr*4 + w;
                int cnt = 0;
                #pragma unroll
                for (int cc = 0; cc < 8; cc++) {
                    float av = adj[i*Nn + cc*32 + lane];
                    unsigned m = __ballot_sync(0xffffffffu, av > 0.0f);
                    if (av > 0.0f) {
                        int pos = cnt + __popc(m & ((1u << lane) - 1u));
                        if (pos < DMAX)
                            g_nbr8[i*DMAX + pos] = (unsigned char)(cc*32 + lane);
                    }
                    cnt += __popc(m);
                }
                if (lane == 0) g_deg[i] = (cnt > DMAX) ? DMAX : cnt;
            }
        } else if (slot < 40) {
            int p = slot - 32;
            #pragma unroll
            for (int k = 0; k < 16; k++) {
                int idx = p*2048 + k*128 + tid;
                int c = idx >> 8, n2 = idx & 255;
                g_lnwT[idx] = lnw[n2*C2c + c];
                g_lnbT[idx] = lnb[n2*C2c + c];
            }
        } else if (slot == 40) {
            #pragma unroll
            for (int r = 0; r < 8; r++) {
                int id = tid + r*128;
                int j = id & 15, c = id >> 4;     // j = h*2 + half
                int h = j >> 1, half = j & 1;
                const float* wr = Wh + (h*64 + c)*64;
                const float* ar = ah + h*128 + half*64;
                float s = 0.0f;
                #pragma unroll
                for (int d2 = 0; d2 < 64; d2++) s = fmaf(wr[d2], ar[d2], s);
                g_vT[c*16 + j] = s;
            }
        }
        return;
    }

    // ---- conv1 + GLU ----
    float*  sx  = sm;                       // 48*128 = 6144 (reused as sxt 16*129)
    float4* swp = (float4*)(sm + 6144);     // 16*24 float4
    int nh = q & 1, ch = q >> 1;
    int n0 = nh * 128;

    #pragma unroll
    for (int u = 0; u < 48; u++) {
        sx[u*128 + tid] = x[((b*C0 + u/3)*Tt + t + (u%3))*Nn + n0 + tid];
    }
    for (int idx = tid; idx < 16*24; idx += 128) {
        int cl = idx / 24, k2 = idx % 24;
        int c = ch*16 + cl;
        float4 v;
        v.x = w1[c*48 + 2*k2];
        v.y = w1[c*48 + 2*k2 + 1];
        v.z = w1[(c+64)*48 + 2*k2];
        v.w = w1[(c+64)*48 + 2*k2 + 1];
        swp[idx] = v;
    }
    __syncthreads();

    int nl = tid;
    float xr[48];
    #pragma unroll
    for (int k = 0; k < 48; k++) xr[k] = sx[k*128 + nl];
    __syncthreads();

    #pragma unroll
    for (int cl = 0; cl < 16; cl++) {
        int c = ch*16 + cl;
        float am = __ldg(b1 + c);
        float ag = __ldg(b1 + c + 64);
        #pragma unroll
        for (int k2 = 0; k2 < 24; k2++) {
            float4 w = swp[cl*24 + k2];
            am = fmaf(xr[2*k2],   w.x, am);
            am = fmaf(xr[2*k2+1], w.y, am);
            ag = fmaf(xr[2*k2],   w.z, ag);
            ag = fmaf(xr[2*k2+1], w.w, ag);
        }
        float xin = (c < C0) ? xr[c*3 + 2] : 0.0f;
        float val = (am + xin) * (1.0f / (1.0f + __expf(-ag)));
        sx[cl*129 + nl] = val;
    }
    __syncthreads();

    int base = ((b*TP + t)*Nn + n0)*C1c + ch*16;
    for (int idx = tid; idx < 128*16; idx += 128) {
        int n2 = idx >> 4, cl = idx & 15;
        g_xg[base + n2*64 + cl] = sx[cl*129 + n2];
    }
}

// ---------------------------------------------------------------------------
// Kernel Agg: all-8-head GAT + residual -> x_s. grid (4, TP, B), 256 threads.
// HALF-WARP PER ROW (2 rows/warp). sxg group-XOR swizzle, aligned LDS128
// gather. In-block e-stage (R9-measured best form).
// ---------------------------------------------------------------------------
__global__ void kAgg() {
    extern __shared__ float sm[];
    float* sxg   = sm;                 // 256*64 = 16384 (swizzled groups)
    float* se2   = sxg + 16384;        // 8*256 = 2048
    float* se1   = se2 + 2048;         // 8*64  = 512
    float* svT   = se1 + 512;          // 64*16 = 1024
    float* stash = svT + 1024;         // 8 warps * 1056 (2x512 p + 128B nbr)
    int tid = threadIdx.x;
    int q = blockIdx.x, t = blockIdx.y, b = blockIdx.z;
    int base = ((b*TP + t)*Nn)*C1c;
    int i0 = q*64;

    for (int idx = tid; idx < 4096; idx += 256) {
        float4 v = ((const float4*)(g_xg + base))[idx];
        int n2 = idx >> 4, g = idx & 15;
        *(float4*)&sxg[n2*64 + ((g ^ (n2 & 15)) << 2)] = v;
    }
    for (int idx = tid; idx < 1024; idx += 256) svT[idx] = g_vT[idx];
    __syncthreads();

    {   // e-stage: e2 for all n, e1 for own 64 rows
        int n = tid;
        int sw = n & 15;
        float a1[8], a2[8];
        #pragma unroll
        for (int h = 0; h < 8; h++) { a1[h] = 0.0f; a2[h] = 0.0f; }
        #pragma unroll
        for (int g = 0; g < 16; g++) {
            float4 xv = *(const float4*)&sxg[n*64 + ((g ^ sw) << 2)];
            float xs[4] = {xv.x, xv.y, xv.z, xv.w};
            #pragma unroll
            for (int e = 0; e < 4; e++) {
                float xe = xs[e];
                const float4* vq = (const float4*)(svT + (4*g + e)*16);
                float4 q0 = vq[0], q1 = vq[1], q2 = vq[2], q3 = vq[3];
                a1[0] = fmaf(xe, q0.x, a1[0]); a2[0] = fmaf(xe, q0.y, a2[0]);
                a1[1] = fmaf(xe, q0.z, a1[1]); a2[1] = fmaf(xe, q0.w, a2[1]);
                a1[2] = fmaf(xe, q1.x, a1[2]); a2[2] = fmaf(xe, q1.y, a2[2]);
                a1[3] = fmaf(xe, q1.z, a1[3]); a2[3] = fmaf(xe, q1.w, a2[3]);
                a1[4] = fmaf(xe, q2.x, a1[4]); a2[4] = fmaf(xe, q2.y, a2[4]);
                a1[5] = fmaf(xe, q2.z, a1[5]); a2[5] = fmaf(xe, q2.w, a2[5]);
                a1[6] = fmaf(xe, q3.x, a1[6]); a2[6] = fmaf(xe, q3.y, a2[6]);
                a1[7] = fmaf(xe, q3.z, a1[7]); a2[7] = fmaf(xe, q3.w, a2[7]);
            }
        }
        #pragma unroll
        for (int h = 0; h < 8; h++) se2[h*256 + n] = a2[h];
        if (n >= i0 && n < i0 + 64) {
            #pragma unroll
            for (int h = 0; h < 8; h++) se1[h*64 + (n - i0)] = a1[h];
        }
    }
    __syncthreads();

    int w = tid >> 5, lane = tid & 31;
    int rowSel = lane >> 4, hl = lane & 15;
    float* spw   = stash + w*1056;          // [spA 512][spB 512][nbr 128B]
    float* spMy  = spw + rowSel*512;
    unsigned char* snbMy = (unsigned char*)(spw + 1024) + rowSel*64;

    for (int rr = 0; rr < 4; rr++) {
        int il = w*8 + rr*2 + rowSel;
        int i = i0 + il;
        int d = g_deg[i];
        int dOther = __shfl_xor_sync(0xffffffffu, d, 16);
        int kmax = (d > dOther) ? d : dOther;

        float e1v[8];
        #pragma unroll
        for (int h = 0; h < 8; h++) e1v[h] = se1[h*64 + il];

        // stage A: slots k = hl + 16s, both rows in parallel
        float S[8];
        #pragma unroll
        for (int h = 0; h < 8; h++) S[h] = 0.0f;
        #pragma unroll
        for (int s = 0; s < 4; s++) {
            int k = hl + s*16;
            float4 pa = {0.f,0.f,0.f,0.f}, pb = {0.f,0.f,0.f,0.f};
            int j = 0;
            if (k < d) {
                j = g_nbr8[i*DMAX + k];
                float s0 = e1v[0] + se2[0*256 + j];
                float s1 = e1v[1] + se2[1*256 + j];
                float s2 = e1v[2] + se2[2*256 + j];
                float s3 = e1v[3] + se2[3*256 + j];
                pa.x = __expf(fmaxf(s0, ALPHA*s0));
                pa.y = __expf(fmaxf(s1, ALPHA*s1));
                pa.z = __expf(fmaxf(s2, ALPHA*s2));
                pa.w = __expf(fmaxf(s3, ALPHA*s3));
                float s4 = e1v[4] + se2[4*256 + j];
                float s5 = e1v[5] + se2[5*256 + j];
                float s6 = e1v[6] + se2[6*256 + j];
                float s7 = e1v[7] + se2[7*256 + j];
                pb.x = __expf(fmaxf(s4, ALPHA*s4));
                pb.y = __expf(fmaxf(s5, ALPHA*s5));
                pb.z = __expf(fmaxf(s6, ALPHA*s6));
                pb.w = __expf(fmaxf(s7, ALPHA*s7));
            }
            snbMy[k] = (unsigned char)j;
            *(float4*)&spMy[k*8]     = pa;
            *(float4*)&spMy[k*8 + 4] = pb;
            S[0] += pa.x; S[1] += pa.y; S[2] += pa.z; S[3] += pa.w;
            S[4] += pb.x; S[5] += pb.y; S[6] += pb.z; S[7] += pb.w;
        }
        // half-warp butterfly: full sums per row
        #pragma unroll
        for (int o = 8; o > 0; o >>= 1) {
            #pragma unroll
            for (int h = 0; h < 8; h++)
                S[h] += __shfl_xor_sync(0xffffffffu, S[h], o);
        }
        __syncwarp();

        // stage B: gather, 4 logical channels per lane (cbase = 4*hl)
        float a[32];
        #pragma unroll
        for (int u = 0; u < 32; u++) a[u] = 0.0f;

        int k = 0;
        for (; k + 2 <= kmax; k += 2) {
            int ja = snbMy[k], jb = snbMy[k+1];
            float4 pa0 = *(const float4*)&spMy[k*8];
            float4 pa1 = *(const float4*)&spMy[k*8 + 4];
            float4 pb0 = *(const float4*)&spMy[(k+1)*8];
            float4 pb1 = *(const float4*)&spMy[(k+1)*8 + 4];
            float4 xa = *(const float4*)&sxg[ja*64 + ((hl ^ (ja & 15)) << 2)];
            float4 xb = *(const float4*)&sxg[jb*64 + ((hl ^ (jb & 15)) << 2)];
            float xav[4] = {xa.x, xa.y, xa.z, xa.w};
            float xbv[4] = {xb.x, xb.y, xb.z, xb.w};
            float pav[8] = {pa0.x, pa0.y, pa0.z, pa0.w, pa1.x, pa1.y, pa1.z, pa1.w};
            float pbv[8] = {pb0.x, pb0.y, pb0.z, pb0.w, pb1.x, pb1.y, pb1.z, pb1.w};
            #pragma unroll
            for (int h = 0; h < 8; h++) {
                #pragma unroll
                for (int e = 0; e < 4; e++) {
                    a[h*4+e] = fmaf(pav[h], xav[e], a[h*4+e]);
                    a[h*4+e] = fmaf(pbv[h], xbv[e], a[h*4+e]);
                }
            }
        }
        if (k < kmax) {
            int j = snbMy[k];
            float4 p0 = *(const float4*)&spMy[k*8];
            float4 p1 = *(const float4*)&spMy[k*8 + 4];
            float4 xv = *(const float4*)&sxg[j*64 + ((hl ^ (j & 15)) << 2)];
            float xsv[4] = {xv.x, xv.y, xv.z, xv.w};
            float pv[8] = {p0.x, p0.y, p0.z, p0.w, p1.x, p1.y, p1.z, p1.w};
            #pragma unroll
            for (int h = 0; h < 8; h++)
                #pragma unroll
                for (int e = 0; e < 4; e++)
                    a[h*4+e] = fmaf(pv[h], xsv[e], a[h*4+e]);
        }

        float rs[8];
        #pragma unroll
        for (int h = 0; h < 8; h++) rs[h] = 1.0f / S[h];
        float r[4] = {0.0f, 0.0f, 0.0f, 0.0f};
        #pragma unroll
        for (int h = 0; h < 8; h++) {
            #pragma unroll
            for (int e = 0; e < 4; e++)
                r[e] += tanh_ap(a[h*4+e] * rs[h]);
        }
        float4 x0 = *(const float4*)&sxg[i*64 + ((hl ^ (i & 15)) << 2)];
        float4 o;
        o.x = x0.x + r[0]*0.125f;
        o.y = x0.y + r[1]*0.125f;
        o.z = x0.z + r[2]*0.125f;
        o.w = x0.w + r[3]*0.125f;
        *(float4*)&g_xs[base + i*64 + 4*hl] = o;
        __syncwarp();   // stash reused next pair
    }
}

// ---------------------------------------------------------------------------
// Kernel D1: conv2 + residual + relu + partial LN stats, t2-paired, n-split.
// grid (8, B, 4), 256 threads. x-loads hoisted per-ci (xv[4]).
// ---------------------------------------------------------------------------
__global__ void kD1(const float* __restrict__ w2, const float* __restrict__ b2) {
    extern __shared__ float sm[];
    float* sx2  = sm;            // 4*128*17 = 8704
    float* sw2a = sm + 8704;     // 4*48*16 = 3072
    __shared__ float red[32];
    int tid = threadIdx.x;
    int t2p = blockIdx.x >> 1, nh = blockIdx.x & 1;
    int b = blockIdx.y, cs = blockIdx.z;
    int half = tid >> 7, nl = tid & 127;
    int t2a = t2p*2;
    int bT = b*TP + t2a;
    int n0 = nh*128;

    for (int idx = tid; idx < 4*48*16; idx += 256) {
        int cout = idx & 15;
        int r = idx >> 4;
        int g = r / 48;
        int ck = r % 48;
        int ci = ck / 3, kt = ck % 3;
        sw2a[idx] = w2[(cs*16 + cout)*(C1c*KTc) + (g*16 + ci)*KTc + kt];
    }

    float acc[16];
    #pragma unroll
    for (int cc = 0; cc < 8; cc++) {
        float bb = __ldg(b2 + cs*16 + half*8 + cc);
        acc[cc] = bb; acc[8 + cc] = bb;
    }

    int ci_s = tid & 15, r0 = tid >> 4;

    #pragma unroll
    for (int g = 0; g < 4; g++) {
        __syncthreads();
        #pragma unroll
        for (int u = 0; u < 32; u++) {
            int linear = r0 + 16*u;
            int kt = linear >> 7, nn = linear & 127;
            sx2[(kt*128 + nn)*17 + ci_s] =
                g_xs[((bT + kt)*Nn + n0 + nn)*C1c + g*16 + ci_s];
        }
        __syncthreads();

        #pragma unroll 4
        for (int ci = 0; ci < 16; ci++) {
            float xv[4];
            #pragma unroll
            for (int kt = 0; kt < 4; kt++)
                xv[kt] = sx2[(kt*128 + nl)*17 + ci];
            #pragma unroll
            for (int kt = 0; kt < 3; kt++) {
                float xva = xv[kt];
                float xvb = xv[kt + 1];
                const float4* wr = (const float4*)(sw2a + (g*48 + ci*3 + kt)*16 + half*8);
                float4 w0 = wr[0], w1v = wr[1];
                acc[0]  = fmaf(xva, w0.x,  acc[0]);
                acc[1]  = fmaf(xva, w0.y,  acc[1]);
                acc[2]  = fmaf(xva, w0.z,  acc[2]);
                acc[3]  = fmaf(xva, w0.w,  acc[3]);
                acc[4]  = fmaf(xva, w1v.x, acc[4]);
                acc[5]  = fmaf(xva, w1v.y, acc[5]);
                acc[6]  = fmaf(xva, w1v.z, acc[6]);
                acc[7]  = fmaf(xva, w1v.w, acc[7]);
                acc[8]  = fmaf(xvb, w0.x,  acc[8]);
                acc[9]  = fmaf(xvb, w0.y,  acc[9]);
                acc[10] = fmaf(xvb, w0.z,  acc[10]);
                acc[11] = fmaf(xvb, w0.w,  acc[11]);
                acc[12] = fmaf(xvb, w1v.x, acc[12]);
                acc[13] = fmaf(xvb, w1v.y, acc[13]);
                acc[14] = fmaf(xvb, w1v.z, acc[14]);
                acc[15] = fmaf(xvb, w1v.w, acc[15]);
            }
        }
        if (g == cs) {
            #pragma unroll
            for (int cc = 0; cc < 8; cc++) {
                acc[cc]     += sx2[(2*128 + nl)*17 + half*8 + cc];
                acc[8 + cc] += sx2[(3*128 + nl)*17 + half*8 + cc];
            }
        }
    }

    float lsA = 0.0f, lssA = 0.0f, lsB = 0.0f, lssB = 0.0f;
    #pragma unroll
    for (int cc = 0; cc < 8; cc++) {
        float va = fmaxf(acc[cc], 0.0f);
        float vb = fmaxf(acc[8 + cc], 0.0f);
        acc[cc] = va; acc[8 + cc] = vb;
        lsA += va; lssA = fmaf(va, va, lssA);
        lsB += vb; lssB = fmaf(vb, vb, lssB);
    }
    #pragma unroll
    for (int o = 16; o > 0; o >>= 1) {
        lsA  += __shfl_xor_sync(0xffffffffu, lsA,  o);
        lssA += __shfl_xor_sync(0xffffffffu, lssA, o);
        lsB  += __shfl_xor_sync(0xffffffffu, lsB,  o);
        lssB += __shfl_xor_sync(0xffffffffu, lssB, o);
    }
    int w = tid >> 5, lane = tid & 31;
    if (lane == 0) {
        red[w] = lsA; red[w + 8] = lssA;
        red[w + 16] = lsB; red[w + 24] = lssB;
    }
    __syncthreads();
    if (tid == 0) {
        float SA = 0, SSA = 0, SB = 0, SSB = 0;
        #pragma unroll
        for (int i = 0; i < 8; i++) {
            SA += red[i]; SSA += red[i + 8];
            SB += red[i + 16]; SSB += red[i + 24];
        }
        int btA = b*T2 + t2a;
        g_psum[((btA*4 + cs)*2 + nh)*2]     = SA;
        g_psum[((btA*4 + cs)*2 + nh)*2 + 1] = SSA;
        g_psum[(((btA+1)*4 + cs)*2 + nh)*2]     = SB;
        g_psum[(((btA+1)*4 + cs)*2 + nh)*2 + 1] = SSB;
    }

    int ybaseA = ((b*T2 + t2a)*C2c + cs*16 + half*8)*Nn + n0;
    int ybaseB = ybaseA + C2c*Nn;
    #pragma unroll
    for (int cc = 0; cc < 8; cc++) {
        g_y[ybaseA + cc*Nn + nl] = acc[cc];
        g_y[ybaseB + cc*Nn + nl] = acc[8 + cc];
    }
}

// ---------------------------------------------------------------------------
// Kernel E: LayerNorm + transposed store. grid (T2, B, 8), 256 threads.
// ---------------------------------------------------------------------------
__global__ void kE(float* __restrict__ out) {
    int t2 = blockIdx.x, b = blockIdx.y, cs = blockIdx.z;  // cs: 8 couts
    int bt = b*T2 + t2;
    float S = 0.0f, SS = 0.0f;
    #pragma unroll
    for (int qq = 0; qq < 8; qq++) {
        S  += g_psum[bt*16 + qq*2];
        SS += g_psum[bt*16 + qq*2 + 1];
    }
    float mu   = S * (1.0f/16384.0f);
    float var  = SS * (1.0f/16384.0f) - mu*mu;
    float rstd = rsqrtf(var + 1e-5f);
    int n = threadIdx.x;
    #pragma unroll
    for (int cc = 0; cc < 8; cc++) {
        int c = cs*8 + cc;
        float yv = (g_y[(bt*C2c + c)*Nn + n] - mu) * rstd;
        out[((b*C2c + c)*T2 + t2)*Nn + n] =
            fmaf(yv, g_lnwT[c*Nn + n], g_lnbT[c*Nn + n]);
    }
}

// ---------------------------------------------------------------------------
extern "C" void kernel_launch(void* const* d_in, const int* in_sizes, int n_in,
                              void* d_out, int out_size) {
    const float* x   = (const float*)d_in[0];
    const float* adj = (const float*)d_in[1];
    const float* w1  = (const float*)d_in[2];
    const float* b1  = (const float*)d_in[3];
    const float* w2  = (const float*)d_in[4];
    const float* b2  = (const float*)d_in[5];
    const float* Wh  = (const float*)d_in[6];
    const float* ah  = (const float*)d_in[7];
    const float* lnw = (const float*)d_in[8];
    const float* lnb = (const float*)d_in[9];
    float* out = (float*)d_out;

    const int smA   = (6144 + 1536) * 4;                        // 30720
    const int smAgg = (16384 + 2048 + 512 + 1024 + 8*1056) * 4; // 113664
    const int smD   = (8704 + 3072) * 4;                        // 47104
    cudaFuncSetAttribute(kA,   cudaFuncAttributeMaxDynamicSharedMemorySize, smA);
    cudaFuncSetAttribute(kAgg, cudaFuncAttributeMaxDynamicSharedMemorySize, smAgg);
    cudaFuncSetAttribute(kD1,  cudaFuncAttributeMaxDynamicSharedMemorySize, smD);

    kA<<<dim3(9, TP, Bn), 128, smA>>>(x, w1, b1, adj, lnw, lnb, Wh, ah);
    kAgg<<<dim3(4, TP, Bn), 256, smAgg>>>();
    kD1<<<dim3(8, Bn, 4), 256, smD>>>(w2, b2);
    kE<<<dim3(T2, Bn, 8), 256>>>(out);
}

// round 15
// speedup vs baseline: 1.3713x; 1.0551x over previous
#include <cuda_runtime.h>
#include <math.h>

#define Bn 8
#define C0 16
#define C1c 64
#define C2c 64
#define Tt 12
#define TP 10
#define T2 8
#define Nn 256
#define KTc 3
#define Hh 8
#define ALPHA 0.2f
#define DMAX 64
#define XSZ (Bn*TP*Nn*C1c)   // 1310720

// scratch (static device allocations — allowed)
__device__ float g_xg[XSZ];          // x_t1 in [b,t,n,c]
__device__ float g_xgT[XSZ];         // x_t1 in [b,t,c,n] (for coalesced e-stage)
__device__ float g_xs[XSZ];          // x_t1 + gat -> x_s
__device__ float g_y[Bn*T2*C2c*Nn];  // conv2+relu output, [bt][c][n]
__device__ float g_psum[Bn*T2*4*2*2];// per (bt, cs, nhalf) partial LN sums
__device__ int   g_deg[Nn];
__device__ unsigned char g_nbr8[Nn*DMAX];
__device__ float g_vT[64*16];        // vT[c*16 + h*2+half]
__device__ float g_lnwT[C2c*Nn];
__device__ float g_lnbT[C2c*Nn];

__device__ __forceinline__ float tanh_ap(float x) {
    float y;
    asm("tanh.approx.f32 %0, %1;" : "=f"(y) : "f"(x));
    return y;
}

// ---------------------------------------------------------------------------
// Kernel A: conv1 (KT=3) + GLU, grid (9, TP, B), 128 threads.
// q<8: conv octant (writes g_xg AND transposed g_xgT). q==8: preprocessing.
// ---------------------------------------------------------------------------
__global__ void kA(const float* __restrict__ x,
                   const float* __restrict__ w1,
                   const float* __restrict__ b1,
                   const float* __restrict__ adj,
                   const float* __restrict__ lnw,
                   const float* __restrict__ lnb,
                   const float* __restrict__ Wh,
                   const float* __restrict__ ah) {
    extern __shared__ float sm[];
    int tid = threadIdx.x;
    int q = blockIdx.x, t = blockIdx.y, b = blockIdx.z;

    if (q == 8) {   // ---- preprocessing slice ----
        int slot = t*8 + b;
        int w = tid >> 5, lane = tid & 31;
        if (slot < 32) {
            #pragma unroll
            for (int rr = 0; rr < 2; rr++) {
                int i = slot*8 + rr*4 + w;
                int cnt = 0;
                #pragma unroll
                for (int cc = 0; cc < 8; cc++) {
                    float av = adj[i*Nn + cc*32 + lane];
                    unsigned m = __ballot_sync(0xffffffffu, av > 0.0f);
                    if (av > 0.0f) {
                        int pos = cnt + __popc(m & ((1u << lane) - 1u));
                        if (pos < DMAX)
                            g_nbr8[i*DMAX + pos] = (unsigned char)(cc*32 + lane);
                    }
                    cnt += __popc(m);
                }
                if (lane == 0) g_deg[i] = (cnt > DMAX) ? DMAX : cnt;
            }
        } else if (slot < 40) {
            int p = slot - 32;
            #pragma unroll
            for (int k = 0; k < 16; k++) {
                int idx = p*2048 + k*128 + tid;
                int c = idx >> 8, n2 = idx & 255;
                g_lnwT[idx] = lnw[n2*C2c + c];
                g_lnbT[idx] = lnb[n2*C2c + c];
            }
        } else if (slot == 40) {
            #pragma unroll
            for (int r = 0; r < 8; r++) {
                int id = tid + r*128;
                int j = id & 15, c = id >> 4;     // j = h*2 + half
                int h = j >> 1, half = j & 1;
                const float* wr = Wh + (h*64 + c)*64;
                const float* ar = ah + h*128 + half*64;
                float s = 0.0f;
                #pragma unroll
                for (int d2 = 0; d2 < 64; d2++) s = fmaf(wr[d2], ar[d2], s);
                g_vT[c*16 + j] = s;
            }
        }
        return;
    }

    // ---- conv1 + GLU ----
    float*  sx  = sm;                       // 48*128 = 6144 (reused as sxt 16*129)
    float4* swp = (float4*)(sm + 6144);     // 16*24 float4
    int nh = q & 1, ch = q >> 1;
    int n0 = nh * 128;

    #pragma unroll
    for (int u = 0; u < 48; u++) {
        sx[u*128 + tid] = x[((b*C0 + u/3)*Tt + t + (u%3))*Nn + n0 + tid];
    }
    for (int idx = tid; idx < 16*24; idx += 128) {
        int cl = idx / 24, k2 = idx % 24;
        int c = ch*16 + cl;
        float4 v;
        v.x = w1[c*48 + 2*k2];
        v.y = w1[c*48 + 2*k2 + 1];
        v.z = w1[(c+64)*48 + 2*k2];
        v.w = w1[(c+64)*48 + 2*k2 + 1];
        swp[idx] = v;
    }
    __syncthreads();

    int nl = tid;
    float xr[48];
    #pragma unroll
    for (int k = 0; k < 48; k++) xr[k] = sx[k*128 + nl];
    __syncthreads();

    #pragma unroll
    for (int cl = 0; cl < 16; cl++) {
        int c = ch*16 + cl;
        float am = __ldg(b1 + c);
        float ag = __ldg(b1 + c + 64);
        #pragma unroll
        for (int k2 = 0; k2 < 24; k2++) {
            float4 w = swp[cl*24 + k2];
            am = fmaf(xr[2*k2],   w.x, am);
            am = fmaf(xr[2*k2+1], w.y, am);
            ag = fmaf(xr[2*k2],   w.z, ag);
            ag = fmaf(xr[2*k2+1], w.w, ag);
        }
        float xin = (c < C0) ? xr[c*3 + 2] : 0.0f;
        float val = (am + xin) * (1.0f / (1.0f + __expf(-ag)));
        sx[cl*129 + nl] = val;
    }
    __syncthreads();

    int base = ((b*TP + t)*Nn + n0)*C1c + ch*16;
    for (int idx = tid; idx < 128*16; idx += 128) {
        int n2 = idx >> 4, cl = idx & 15;
        g_xg[base + n2*64 + cl] = sx[cl*129 + n2];
    }
    // transposed copy: g_xgT[bt][c][n]
    int baseT = (b*TP + t)*Nn*C1c + (ch*16)*256 + n0;
    #pragma unroll
    for (int p = 0; p < 16; p++) {
        g_xgT[baseT + p*256 + tid] = sx[p*129 + tid];
    }
}

// ---------------------------------------------------------------------------
// Kernel Agg: all-8-head GAT + residual -> x_s. grid (4, TP, B), 256 threads.
// FULL WARP PER ROW, 8 rows/warp. NO xg smem copy: gather reads g_xg rows
// directly (coalesced 256B row per edge, L1-resident: 3 blocks x 64KB slices
// fit 228KB L1). e-stage reads transposed g_xgT coalesced. smem ~31KB ->
// occupancy limited by regs (~3 blocks/SM).
// ---------------------------------------------------------------------------
__global__ void kAgg() {
    extern __shared__ float sm[];
    float* se2   = sm;            // 8*256 = 2048
    float* se1   = sm + 2048;     // 8*64  = 512
    float* svT   = sm + 2560;     // 64*16 = 1024
    float* stash = sm + 3584;     // 8 warps * 528 (512 p + 64B nbr)
    int tid = threadIdx.x;
    int q = blockIdx.x, t = blockIdx.y, b = blockIdx.z;
    int bt = b*TP + t;
    int base = bt*Nn*C1c;
    int i0 = q*64;

    for (int idx = tid; idx < 1024; idx += 256) svT[idx] = g_vT[idx];
    __syncthreads();

    {   // e-stage: e2 for all n, e1 for own 64 rows; x from g_xgT (coalesced)
        int n = tid;
        const float* xT = g_xgT + bt*16384;
        float a1[8], a2[8];
        #pragma unroll
        for (int h = 0; h < 8; h++) { a1[h] = 0.0f; a2[h] = 0.0f; }
        #pragma unroll 8
        for (int c = 0; c < 64; c++) {
            float xe = xT[c*256 + n];
            const float4* vq = (const float4*)(svT + c*16);
            float4 q0 = vq[0], q1 = vq[1], q2 = vq[2], q3 = vq[3];
            a1[0] = fmaf(xe, q0.x, a1[0]); a2[0] = fmaf(xe, q0.y, a2[0]);
            a1[1] = fmaf(xe, q0.z, a1[1]); a2[1] = fmaf(xe, q0.w, a2[1]);
            a1[2] = fmaf(xe, q1.x, a1[2]); a2[2] = fmaf(xe, q1.y, a2[2]);
            a1[3] = fmaf(xe, q1.z, a1[3]); a2[3] = fmaf(xe, q1.w, a2[3]);
            a1[4] = fmaf(xe, q2.x, a1[4]); a2[4] = fmaf(xe, q2.y, a2[4]);
            a1[5] = fmaf(xe, q2.z, a1[5]); a2[5] = fmaf(xe, q2.w, a2[5]);
            a1[6] = fmaf(xe, q3.x, a1[6]); a2[6] = fmaf(xe, q3.y, a2[6]);
            a1[7] = fmaf(xe, q3.z, a1[7]); a2[7] = fmaf(xe, q3.w, a2[7]);
        }
        #pragma unroll
        for (int h = 0; h < 8; h++) se2[h*256 + n] = a2[h];
        if (n >= i0 && n < i0 + 64) {
            #pragma unroll
            for (int h = 0; h < 8; h++) se1[h*64 + (n - i0)] = a1[h];
        }
    }
    __syncthreads();

    int w = tid >> 5, lane = tid & 31;
    float* sp = stash + w*528;
    unsigned char* snb = (unsigned char*)(sp + 512);
    int c0 = 2*lane;

    for (int rr = 0; rr < 8; rr++) {
        int il = w*8 + rr;
        int i = i0 + il;
        int d = g_deg[i];
        if (lane < d) snb[lane] = g_nbr8[i*DMAX + lane];
        if (lane + 32 < d) snb[lane + 32] = g_nbr8[i*DMAX + lane + 32];
        __syncwarp();

        float e1v[8];
        #pragma unroll
        for (int h = 0; h < 8; h++) e1v[h] = se1[h*64 + il];

        // stage A: p[k][h] + per-lane partial sums S[h]
        float S[8];
        #pragma unroll
        for (int h = 0; h < 8; h++) S[h] = 0.0f;
        #pragma unroll
        for (int kk = 0; kk < 2; kk++) {
            int k = lane + kk*32;
            if (k < d) {
                int j = snb[k];
                float4 pa, pb;
                {
                    float s0 = e1v[0] + se2[0*256 + j];
                    float s1 = e1v[1] + se2[1*256 + j];
                    float s2 = e1v[2] + se2[2*256 + j];
                    float s3 = e1v[3] + se2[3*256 + j];
                    pa.x = __expf(fmaxf(s0, ALPHA*s0));
                    pa.y = __expf(fmaxf(s1, ALPHA*s1));
                    pa.z = __expf(fmaxf(s2, ALPHA*s2));
                    pa.w = __expf(fmaxf(s3, ALPHA*s3));
                }
                {
                    float s4 = e1v[4] + se2[4*256 + j];
                    float s5 = e1v[5] + se2[5*256 + j];
                    float s6 = e1v[6] + se2[6*256 + j];
                    float s7 = e1v[7] + se2[7*256 + j];
                    pb.x = __expf(fmaxf(s4, ALPHA*s4));
                    pb.y = __expf(fmaxf(s5, ALPHA*s5));
                    pb.z = __expf(fmaxf(s6, ALPHA*s6));
                    pb.w = __expf(fmaxf(s7, ALPHA*s7));
                }
                *(float4*)&sp[k*8]     = pa;
                *(float4*)&sp[k*8 + 4] = pb;
                S[0] += pa.x; S[1] += pa.y; S[2] += pa.z; S[3] += pa.w;
                S[4] += pb.x; S[5] += pb.y; S[6] += pb.z; S[7] += pb.w;
            }
        }
        #pragma unroll
        for (int o = 16; o > 0; o >>= 1) {
            #pragma unroll
            for (int h = 0; h < 8; h++)
                S[h] += __shfl_xor_sync(0xffffffffu, S[h], o);
        }
        __syncwarp();

        // stage B: gather from GLOBAL xg (L1-resident rows), unrolled x2
        float a[16];
        #pragma unroll
        for (int u = 0; u < 16; u++) a[u] = 0.0f;

        const float* xrow = g_xg + base;
        int k = 0;
        for (; k + 2 <= d; k += 2) {
            int ja = snb[k], jb = snb[k+1];
            float2 xa = *(const float2*)&xrow[ja*64 + c0];
            float2 xb = *(const float2*)&xrow[jb*64 + c0];
            float4 pa0 = *(const float4*)&sp[k*8];
            float4 pa1 = *(const float4*)&sp[k*8 + 4];
            float4 pb0 = *(const float4*)&sp[(k+1)*8];
            float4 pb1 = *(const float4*)&sp[(k+1)*8 + 4];
            a[0]  = fmaf(pa0.x, xa.x, a[0]);   a[1]  = fmaf(pa0.x, xa.y, a[1]);
            a[2]  = fmaf(pa0.y, xa.x, a[2]);   a[3]  = fmaf(pa0.y, xa.y, a[3]);
            a[4]  = fmaf(pa0.z, xa.x, a[4]);   a[5]  = fmaf(pa0.z, xa.y, a[5]);
            a[6]  = fmaf(pa0.w, xa.x, a[6]);   a[7]  = fmaf(pa0.w, xa.y, a[7]);
            a[8]  = fmaf(pa1.x, xa.x, a[8]);   a[9]  = fmaf(pa1.x, xa.y, a[9]);
            a[10] = fmaf(pa1.y, xa.x, a[10]);  a[11] = fmaf(pa1.y, xa.y, a[11]);
            a[12] = fmaf(pa1.z, xa.x, a[12]);  a[13] = fmaf(pa1.z, xa.y, a[13]);
            a[14] = fmaf(pa1.w, xa.x, a[14]);  a[15] = fmaf(pa1.w, xa.y, a[15]);
            a[0]  = fmaf(pb0.x, xb.x, a[0]);   a[1]  = fmaf(pb0.x, xb.y, a[1]);
            a[2]  = fmaf(pb0.y, xb.x, a[2]);   a[3]  = fmaf(pb0.y, xb.y, a[3]);
            a[4]  = fmaf(pb0.z, xb.x, a[4]);   a[5]  = fmaf(pb0.z, xb.y, a[5]);
            a[6]  = fmaf(pb0.w, xb.x, a[6]);   a[7]  = fmaf(pb0.w, xb.y, a[7]);
            a[8]  = fmaf(pb1.x, xb.x, a[8]);   a[9]  = fmaf(pb1.x, xb.y, a[9]);
            a[10] = fmaf(pb1.y, xb.x, a[10]);  a[11] = fmaf(pb1.y, xb.y, a[11]);
            a[12] = fmaf(pb1.z, xb.x, a[12]);  a[13] = fmaf(pb1.z, xb.y, a[13]);
            a[14] = fmaf(pb1.w, xb.x, a[14]);  a[15] = fmaf(pb1.w, xb.y, a[15]);
        }
        if (k < d) {
            int j = snb[k];
            float2 xv = *(const float2*)&xrow[j*64 + c0];
            float4 p0 = *(const float4*)&sp[k*8];
            float4 p1 = *(const float4*)&sp[k*8 + 4];
            a[0]  = fmaf(p0.x, xv.x, a[0]);   a[1]  = fmaf(p0.x, xv.y, a[1]);
            a[2]  = fmaf(p0.y, xv.x, a[2]);   a[3]  = fmaf(p0.y, xv.y, a[3]);
            a[4]  = fmaf(p0.z, xv.x, a[4]);   a[5]  = fmaf(p0.z, xv.y, a[5]);
            a[6]  = fmaf(p0.w, xv.x, a[6]);   a[7]  = fmaf(p0.w, xv.y, a[7]);
            a[8]  = fmaf(p1.x, xv.x, a[8]);   a[9]  = fmaf(p1.x, xv.y, a[9]);
            a[10] = fmaf(p1.y, xv.x, a[10]);  a[11] = fmaf(p1.y, xv.y, a[11]);
            a[12] = fmaf(p1.z, xv.x, a[12]);  a[13] = fmaf(p1.z, xv.y, a[13]);
            a[14] = fmaf(p1.w, xv.x, a[14]);  a[15] = fmaf(p1.w, xv.y, a[15]);
        }

        float rx = 0.0f, ry = 0.0f;
        #pragma unroll
        for (int h = 0; h < 8; h++) {
            float rs = 1.0f / S[h];
            rx += tanh_ap(a[2*h]     * rs);
            ry += tanh_ap(a[2*h + 1] * rs);
        }
        float2 x0 = *(const float2*)&xrow[i*64 + c0];
        float2 o;
        o.x = x0.x + rx * 0.125f;
        o.y = x0.y + ry * 0.125f;
        *(float2*)&g_xs[base + i*64 + c0] = o;
        __syncwarp();   // sp/snb reused next row
    }
}

// ---------------------------------------------------------------------------
// Kernel D1: conv2 + residual + relu + partial LN stats, t2-paired, n-split.
// grid (8, B, 4), 256 threads. (R14-identical.)
// ---------------------------------------------------------------------------
__global__ void kD1(const float* __restrict__ w2, const float* __restrict__ b2) {
    extern __shared__ float sm[];
    float* sx2  = sm;            // 4*128*17 = 8704
    float* sw2a = sm + 8704;     // 4*48*16 = 3072
    __shared__ float red[32];
    int tid = threadIdx.x;
    int t2p = blockIdx.x >> 1, nh = blockIdx.x & 1;
    int b = blockIdx.y, cs = blockIdx.z;
    int half = tid >> 7, nl = tid & 127;
    int t2a = t2p*2;
    int bT = b*TP + t2a;
    int n0 = nh*128;

    for (int idx = tid; idx < 4*48*16; idx += 256) {
        int cout = idx & 15;
        int r = idx >> 4;
        int g = r / 48;
        int ck = r % 48;
        int ci = ck / 3, kt = ck % 3;
        sw2a[idx] = w2[(cs*16 + cout)*(C1c*KTc) + (g*16 + ci)*KTc + kt];
    }

    float acc[16];
    #pragma unroll
    for (int cc = 0; cc < 8; cc++) {
        float bb = __ldg(b2 + cs*16 + half*8 + cc);
        acc[cc] = bb; acc[8 + cc] = bb;
    }

    int ci_s = tid & 15, r0 = tid >> 4;

    #pragma unroll
    for (int g = 0; g < 4; g++) {
        __syncthreads();
        #pragma unroll
        for (int u = 0; u < 32; u++) {
            int linear = r0 + 16*u;
            int kt = linear >> 7, nn = linear & 127;
            sx2[(kt*128 + nn)*17 + ci_s] =
                g_xs[((bT + kt)*Nn + n0 + nn)*C1c + g*16 + ci_s];
        }
        __syncthreads();

        #pragma unroll 4
        for (int ci = 0; ci < 16; ci++) {
            float xv[4];
            #pragma unroll
            for (int kt = 0; kt < 4; kt++)
                xv[kt] = sx2[(kt*128 + nl)*17 + ci];
            #pragma unroll
            for (int kt = 0; kt < 3; kt++) {
                float xva = xv[kt];
                float xvb = xv[kt + 1];
                const float4* wr = (const float4*)(sw2a + (g*48 + ci*3 + kt)*16 + half*8);
                float4 w0 = wr[0], w1v = wr[1];
                acc[0]  = fmaf(xva, w0.x,  acc[0]);
                acc[1]  = fmaf(xva, w0.y,  acc[1]);
                acc[2]  = fmaf(xva, w0.z,  acc[2]);
                acc[3]  = fmaf(xva, w0.w,  acc[3]);
                acc[4]  = fmaf(xva, w1v.x, acc[4]);
                acc[5]  = fmaf(xva, w1v.y, acc[5]);
                acc[6]  = fmaf(xva, w1v.z, acc[6]);
                acc[7]  = fmaf(xva, w1v.w, acc[7]);
                acc[8]  = fmaf(xvb, w0.x,  acc[8]);
                acc[9]  = fmaf(xvb, w0.y,  acc[9]);
                acc[10] = fmaf(xvb, w0.z,  acc[10]);
                acc[11] = fmaf(xvb, w0.w,  acc[11]);
                acc[12] = fmaf(xvb, w1v.x, acc[12]);
                acc[13] = fmaf(xvb, w1v.y, acc[13]);
                acc[14] = fmaf(xvb, w1v.z, acc[14]);
                acc[15] = fmaf(xvb, w1v.w, acc[15]);
            }
        }
        if (g == cs) {
            #pragma unroll
            for (int cc = 0; cc < 8; cc++) {
                acc[cc]     += sx2[(2*128 + nl)*17 + half*8 + cc];
                acc[8 + cc] += sx2[(3*128 + nl)*17 + half*8 + cc];
            }
        }
    }

    float lsA = 0.0f, lssA = 0.0f, lsB = 0.0f, lssB = 0.0f;
    #pragma unroll
    for (int cc = 0; cc < 8; cc++) {
        float va = fmaxf(acc[cc], 0.0f);
        float vb = fmaxf(acc[8 + cc], 0.0f);
        acc[cc] = va; acc[8 + cc] = vb;
        lsA += va; lssA = fmaf(va, va, lssA);
        lsB += vb; lssB = fmaf(vb, vb, lssB);
    }
    #pragma unroll
    for (int o = 16; o > 0; o >>= 1) {
        lsA  += __shfl_xor_sync(0xffffffffu, lsA,  o);
        lssA += __shfl_xor_sync(0xffffffffu, lssA, o);
        lsB  += __shfl_xor_sync(0xffffffffu, lsB,  o);
        lssB += __shfl_xor_sync(0xffffffffu, lssB, o);
    }
    int w = tid >> 5, lane = tid & 31;
    if (lane == 0) {
        red[w] = lsA; red[w + 8] = lssA;
        red[w + 16] = lsB; red[w + 24] = lssB;
    }
    __syncthreads();
    if (tid == 0) {
        float SA = 0, SSA = 0, SB = 0, SSB = 0;
        #pragma unroll
        for (int i = 0; i < 8; i++) {
            SA += red[i]; SSA += red[i + 8];
            SB += red[i + 16]; SSB += red[i + 24];
        }
        int btA = b*T2 + t2a;
        g_psum[((btA*4 + cs)*2 + nh)*2]     = SA;
        g_psum[((btA*4 + cs)*2 + nh)*2 + 1] = SSA;
        g_psum[(((btA+1)*4 + cs)*2 + nh)*2]     = SB;
        g_psum[(((btA+1)*4 + cs)*2 + nh)*2 + 1] = SSB;
    }

    int ybaseA = ((b*T2 + t2a)*C2c + cs*16 + half*8)*Nn + n0;
    int ybaseB = ybaseA + C2c*Nn;
    #pragma unroll
    for (int cc = 0; cc < 8; cc++) {
        g_y[ybaseA + cc*Nn + nl] = acc[cc];
        g_y[ybaseB + cc*Nn + nl] = acc[8 + cc];
    }
}

// ---------------------------------------------------------------------------
// Kernel E: LayerNorm + transposed store. grid (T2, B, 8), 256 threads.
// ---------------------------------------------------------------------------
__global__ void kE(float* __restrict__ out) {
    int t2 = blockIdx.x, b = blockIdx.y, cs = blockIdx.z;  // cs: 8 couts
    int bt = b*T2 + t2;
    float S = 0.0f, SS = 0.0f;
    #pragma unroll
    for (int qq = 0; qq < 8; qq++) {
        S  += g_psum[bt*16 + qq*2];
        SS += g_psum[bt*16 + qq*2 + 1];
    }
    float mu   = S * (1.0f/16384.0f);
    float var  = SS * (1.0f/16384.0f) - mu*mu;
    float rstd = rsqrtf(var + 1e-5f);
    int n = threadIdx.x;
    #pragma unroll
    for (int cc = 0; cc < 8; cc++) {
        int c = cs*8 + cc;
        float yv = (g_y[(bt*C2c + c)*Nn + n] - mu) * rstd;
        out[((b*C2c + c)*T2 + t2)*Nn + n] =
            fmaf(yv, g_lnwT[c*Nn + n], g_lnbT[c*Nn + n]);
    }
}

// ---------------------------------------------------------------------------
extern "C" void kernel_launch(void* const* d_in, const int* in_sizes, int n_in,
                              void* d_out, int out_size) {
    const float* x   = (const float*)d_in[0];
    const float* adj = (const float*)d_in[1];
    const float* w1  = (const float*)d_in[2];
    const float* b1  = (const float*)d_in[3];
    const float* w2  = (const float*)d_in[4];
    const float* b2  = (const float*)d_in[5];
    const float* Wh  = (const float*)d_in[6];
    const float* ah  = (const float*)d_in[7];
    const float* lnw = (const float*)d_in[8];
    const float* lnb = (const float*)d_in[9];
    float* out = (float*)d_out;

    const int smA   = (6144 + 1536) * 4;                 // 30720
    const int smAgg = (2048 + 512 + 1024 + 8*528) * 4;   // 31232
    const int smD   = (8704 + 3072) * 4;                 // 47104
    cudaFuncSetAttribute(kA,   cudaFuncAttributeMaxDynamicSharedMemorySize, smA);
    cudaFuncSetAttribute(kAgg, cudaFuncAttributeMaxDynamicSharedMemorySize, smAgg);
    cudaFuncSetAttribute(kD1,  cudaFuncAttributeMaxDynamicSharedMemorySize, smD);

    kA<<<dim3(9, TP, Bn), 128, smA>>>(x, w1, b1, adj, lnw, lnb, Wh, ah);
    kAgg<<<dim3(4, TP, Bn), 256, smAgg>>>();
    kD1<<<dim3(8, Bn, 4), 256, smD>>>(w2, b2);
    kE<<<dim3(T2, Bn, 8), 256>>>(out);
}